// round 11
// baseline (speedup 1.0000x reference)
#include <cuda_runtime.h>
#include <cuda_bf16.h>
#include <stdint.h>

#define NN 96
#define DD 64
#define CC 30
#define PREP_BLOCKS 144                      // 36 mat + 12 label + 96 idle-then-cmask
#define TOTAL_BLOCKS (PREP_BLOCKS + NN*NN)   // 9360

// Scratch (__device__ globals; no allocation allowed)
__device__ float    g_mat[NN * NN];
__device__ unsigned g_smask[NN * 3];
__device__ unsigned g_dmask[NN * 3];
__device__ unsigned g_cmask[NN * NN * 4];  // 96-bit mask per (i,p), stride 4 words
__device__ unsigned g_count;               // prep barrier (monotonic; +144 per launch)
__device__ unsigned g_done;                // cmask-ready counter (reset at kernel end)
__device__ unsigned g_fin;                 // completion counter (reset at kernel end)

// ---------------------------------------------------------------------------
// ONE kernel, 9360 blocks x 256 threads, __launch_bounds__(256,8) so the
// writer path keeps 8 blocks/SM (regs capped at 32).
//  blocks 0..143  : prep. 0..35 mat (one output/thread, global reads, no big
//                   smem), 36..47 label masks (warp ballots, global reads),
//                   48..143 straight to the prep barrier. After the barrier
//                   each block computes eps redundantly (bit-identical) and
//                   blocks 0..95 build cmask for one anchor each. Then +1 on
//                   g_done.
//  blocks 144..   : writer, one FULL slab (i,j), j DESCENDING:
//                   zero prefix -> nanosleep-poll g_done==144 -> data suffix.
//  tail           : last finisher resets g_done/g_fin (replay-safe).
// ---------------------------------------------------------------------------
__global__ __launch_bounds__(256, 8) void fused(const float* __restrict__ logits,
                                                const float* __restrict__ labels,
                                                float4* __restrict__ out) {
    const int tid = threadIdx.x;
    const int bid = blockIdx.x;

    if (bid >= PREP_BLOCKS) {
        // ========================= writer =========================
        __shared__ unsigned sw[NN * 3];
        const int zid = bid - PREP_BLOCKS;       // 0..9215
        const int q   = zid / NN;                // 0..95
        const int i   = zid - q * NN;            // anchor
        const int j   = NN - 1 - q;              // j descending with bid
        float4* o = out + ((size_t)i * NN + j) * 2304;
        const int len1 = (j + 1) * 24;           // zero prefix (k <= j)

        const float4 z4 = make_float4(0.f, 0.f, 0.f, 0.f);
        for (int pos = tid; pos < len1; pos += 256)
            __stcs(o + pos, z4);

        if (j < NN - 1) {
            if (tid == 0) {
                while (*(volatile unsigned*)&g_done < PREP_BLOCKS)
                    __nanosleep(256);            // backoff: don't burn L2 BW
                __threadfence();                 // acquire cmask
            }
            __syncthreads();

            const int r2w    = (i * NN + j) << 2;
            const int ibase4 = (i * NN) << 2;
            for (int t = tid; t < NN * 3; t += 256) {
                int k  = t / 3;
                int wd = t - k * 3;
                sw[t] = g_cmask[r2w + wd] & g_cmask[ibase4 + (k << 2) + wd];
            }
            __syncthreads();

            const unsigned ONEF = 0x3f800000u;
            for (int pos = len1 + tid; pos < 2304; pos += 256) {
                int k = pos / 24;
                int r = pos - k * 24;
                unsigned w = sw[k * 3 + (r >> 3)];
                unsigned b = w >> ((r & 7) * 4);
                float4 v;
                v.x = __uint_as_float(ONEF & (0u - (b & 1u)));
                v.y = __uint_as_float(ONEF & (0u - ((b >> 1) & 1u)));
                v.z = __uint_as_float(ONEF & (0u - ((b >> 2) & 1u)));
                v.w = __uint_as_float(ONEF & (0u - ((b >> 3) & 1u)));
                __stcs(o + pos, v);
            }
        }
    } else {
        // ========================= prep (0..143) =========================
        __shared__ float    s_rnum[NN], s_rq[NN];
        __shared__ float    s_eps;
        __shared__ float    srow[NN];
        __shared__ unsigned sm[3], dm[3];

        const int warp = tid >> 5, lane = tid & 31;

        if (bid < 36) {
            // ---- mat: one output per thread; rows read from global (L1).
            // Norm sums and dot products keep the exact d-ascending order.
            const int outp = bid * 256 + tid;         // 0..9215
            const int r = outp / NN;
            const int c = outp - r * NN;
            const float* rowr = logits + r * DD;
            const float* rowc = logits + c * DD;
            float sr = 0.f, sc = 0.f, acc = 0.f;
            #pragma unroll
            for (int d = 0; d < DD; d++) {
                float vr = __ldg(rowr + d);
                float vc = __ldg(rowc + d);
                sr  += vr * vr;
                sc  += vc * vc;
                acc += vr * vc;
            }
            g_mat[outp] = -acc * rsqrtf(sr) * rsqrtf(sc);
        } else if (bid < 48) {
            // ---- labels: one warp per row, 8 rows per block, global reads.
            const int i = (bid - 36) * 8 + warp;      // row 0..95
            const float* li = labels + i * CC;
            #pragma unroll
            for (int wd = 0; wd < 3; wd++) {
                int j = wd * 32 + lane;
                const float* lj = labels + j * CC;
                float acc = 0.f;
                #pragma unroll
                for (int cc = 0; cc < CC; cc++) acc += __ldg(li + cc) * __ldg(lj + cc);
                bool same_raw = acc > 0.f;
                unsigned sb = __ballot_sync(0xffffffffu, same_raw && (j != i));
                unsigned db = __ballot_sync(0xffffffffu, !same_raw);
                if (lane == 0) {
                    g_smask[i * 3 + wd] = sb;
                    g_dmask[i * 3 + wd] = db;
                }
            }
        }
        // blocks 48..143 arrive directly at the barrier.

        // ---- barrier among the 144 prep blocks (co-resident in wave 1) ----
        __threadfence();                              // publish mat / masks
        __syncthreads();
        if (tid == 0) {
            unsigned prev   = atomicAdd(&g_count, 1u);
            unsigned target = (prev / PREP_BLOCKS + 1u) * PREP_BLOCKS;
            while (*(volatile unsigned*)&g_count < target)
                __nanosleep(64);
            __threadfence();                          // acquire
        }
        __syncthreads();

        // ---- epsilon: identical math/order in every block -> deterministic ----
        for (int i = warp; i < NN; i += 8) {
            float S = 0.f, ds = 0.f, ms = 0.f, md = 0.f;
            #pragma unroll
            for (int jj = 0; jj < 3; jj++) {
                float mv = g_mat[i * NN + jj * 32 + lane];
                if ((g_smask[i * 3 + jj] >> lane) & 1u) { S += 1.f; ms += mv; }
                if ((g_dmask[i * 3 + jj] >> lane) & 1u) { ds += 1.f; md += mv; }
            }
            #pragma unroll
            for (int o = 16; o; o >>= 1) {
                S  += __shfl_xor_sync(0xffffffffu, S,  o);
                ds += __shfl_xor_sync(0xffffffffu, ds, o);
                ms += __shfl_xor_sync(0xffffffffu, ms, o);
                md += __shfl_xor_sync(0xffffffffu, md, o);
            }
            if (lane == 0) {
                s_rnum[i] = (S - 1.f) * (S * md - ms * ds);
                s_rq[i]   = 0.5f * S * (S - 1.f) * ds;
            }
        }
        __syncthreads();
        if (tid == 0) {   // serial reduce: identical order every block
            float num = 0.f, q = 0.f;
            for (int i = 0; i < NN; i++) { num += s_rnum[i]; q += s_rq[i]; }
            float mean_delta = num / fmaxf(2.f * q, 1.f);
            s_eps = fmaxf(mean_delta * 0.5f, 0.f);   // relu(mean_delta / K_DELTA)
        }
        __syncthreads();
        const float eps = s_eps;

        // ---- cmask: blocks 0..95 own one anchor each ----
        if (bid < NN) {
            const int ianc = bid;
            if (tid < NN) srow[tid] = g_mat[ianc * NN + tid];
            if (tid >= NN && tid < NN + 3) {
                sm[tid - NN] = g_smask[ianc * 3 + (tid - NN)];
                dm[tid - NN] = g_dmask[ianc * 3 + (tid - NN)];
            }
            __syncthreads();
            for (int p = warp; p < NN; p += 8) {
                unsigned sp = (sm[p >> 5] >> (p & 31)) & 1u;
                float matp = srow[p];
                #pragma unroll
                for (int wd = 0; wd < 3; wd++) {
                    float m = srow[wd * 32 + lane] - matp;
                    bool cc = sp && (((dm[wd] >> lane) & 1u) != 0u) && (m > 0.f) && (m <= eps);
                    unsigned b = __ballot_sync(0xffffffffu, cc);
                    if (lane == 0) g_cmask[(ianc * NN + p) * 4 + wd] = b;
                }
            }
        }

        // ---- publish cmask ready ----
        __threadfence();
        __syncthreads();
        if (tid == 0) atomicAdd(&g_done, 1u);
    }

    // ========================= tail: replay-safe reset =========================
    __syncthreads();
    if (tid == 0) {
        __threadfence();
        unsigned prev = atomicAdd(&g_fin, 1u);
        if (prev == (unsigned)TOTAL_BLOCKS - 1u) {
            // Last finisher: every other block already passed its waits.
            g_done = 0u;
            g_fin  = 0u;
            __threadfence();
        }
    }
}

// ---------------------------------------------------------------------------
extern "C" void kernel_launch(void* const* d_in, const int* in_sizes, int n_in,
                              void* d_out, int out_size) {
    const float* logits = (const float*)d_in[0];   // [96,64]
    const float* labels = (const float*)d_in[1];   // [96,30]

    fused<<<TOTAL_BLOCKS, 256>>>(logits, labels, (float4*)d_out);
}

// round 12
// speedup vs baseline: 1.0602x; 1.0602x over previous
#include <cuda_runtime.h>
#include <cuda_bf16.h>
#include <stdint.h>

#define NN 96
#define DD 64
#define CC 30
#define PREP_BLOCKS 144   // 36 mat + 12 label + 96 barrier-then-cmask

// Scratch (__device__ globals; no allocation allowed)
__device__ float    g_mat[NN * NN];
__device__ unsigned g_smask[NN * 3];
__device__ unsigned g_dmask[NN * 3];
__device__ unsigned g_cmask[NN * NN * 4];  // 96-bit mask per (i,p), stride 4 words
__device__ unsigned g_count;               // prep barrier (monotonic; +144 per launch)

// ---------------------------------------------------------------------------
// prep: 144 blocks x 256, lightweight (global reads, tiny smem).
//   blocks 0..35  : cosine mat, one output per thread (36*256 = 9216).
//   blocks 36..47 : label masks via warp ballots (8 rows per block).
//   blocks 48..143: straight to the barrier (extra arrivals keep the wave
//                   wide so cmask below has 96 workers).
//   After the barrier: every block computes eps redundantly (bit-identical
//   order -> deterministic); blocks 0..95 build cmask for one anchor each.
// ---------------------------------------------------------------------------
__global__ __launch_bounds__(256) void prep(const float* __restrict__ logits,
                                            const float* __restrict__ labels) {
    __shared__ float    s_rnum[NN], s_rq[NN];
    __shared__ float    s_eps;
    __shared__ float    srow[NN];
    __shared__ unsigned sm[3], dm[3];

    const int tid  = threadIdx.x;
    const int bid  = blockIdx.x;
    const int warp = tid >> 5, lane = tid & 31;

    if (bid < 36) {
        // ---- mat: one output per thread; rows read from global (L1/L2).
        // Norm sums and dot products keep the exact d-ascending order.
        const int outp = bid * 256 + tid;             // 0..9215
        const int r = outp / NN;
        const int c = outp - r * NN;
        const float* rowr = logits + r * DD;
        const float* rowc = logits + c * DD;
        float sr = 0.f, sc = 0.f, acc = 0.f;
        #pragma unroll
        for (int d = 0; d < DD; d++) {
            float vr = __ldg(rowr + d);
            float vc = __ldg(rowc + d);
            sr  += vr * vr;
            sc  += vc * vc;
            acc += vr * vc;
        }
        g_mat[outp] = -acc * rsqrtf(sr) * rsqrtf(sc);
    } else if (bid < 48) {
        // ---- labels: one warp per row, 8 rows per block, global reads.
        const int i = (bid - 36) * 8 + warp;          // row 0..95
        const float* li = labels + i * CC;
        #pragma unroll
        for (int wd = 0; wd < 3; wd++) {
            int j = wd * 32 + lane;
            const float* lj = labels + j * CC;
            float acc = 0.f;
            #pragma unroll
            for (int cc = 0; cc < CC; cc++) acc += __ldg(li + cc) * __ldg(lj + cc);
            bool same_raw = acc > 0.f;
            unsigned sb = __ballot_sync(0xffffffffu, same_raw && (j != i));
            unsigned db = __ballot_sync(0xffffffffu, !same_raw);
            if (lane == 0) {
                g_smask[i * 3 + wd] = sb;
                g_dmask[i * 3 + wd] = db;
            }
        }
    }
    // blocks 48..143 arrive directly at the barrier.

    // ---- barrier among the 144 prep blocks (co-resident: one wave) ----
    __threadfence();                                  // publish mat / masks
    __syncthreads();
    if (tid == 0) {
        unsigned prev   = atomicAdd(&g_count, 1u);
        unsigned target = (prev / PREP_BLOCKS + 1u) * PREP_BLOCKS;
        while (*(volatile unsigned*)&g_count < target)
            __nanosleep(64);
        __threadfence();                              // acquire
    }
    __syncthreads();

    // ---- epsilon: identical math/order in every block -> deterministic ----
    for (int i = warp; i < NN; i += 8) {
        float S = 0.f, ds = 0.f, ms = 0.f, md = 0.f;
        #pragma unroll
        for (int jj = 0; jj < 3; jj++) {
            float mv = g_mat[i * NN + jj * 32 + lane];
            if ((g_smask[i * 3 + jj] >> lane) & 1u) { S += 1.f; ms += mv; }
            if ((g_dmask[i * 3 + jj] >> lane) & 1u) { ds += 1.f; md += mv; }
        }
        #pragma unroll
        for (int o = 16; o; o >>= 1) {
            S  += __shfl_xor_sync(0xffffffffu, S,  o);
            ds += __shfl_xor_sync(0xffffffffu, ds, o);
            ms += __shfl_xor_sync(0xffffffffu, ms, o);
            md += __shfl_xor_sync(0xffffffffu, md, o);
        }
        if (lane == 0) {
            s_rnum[i] = (S - 1.f) * (S * md - ms * ds);
            s_rq[i]   = 0.5f * S * (S - 1.f) * ds;
        }
    }
    __syncthreads();
    if (tid == 0) {   // serial reduce: identical order every block
        float num = 0.f, q = 0.f;
        for (int i = 0; i < NN; i++) { num += s_rnum[i]; q += s_rq[i]; }
        float mean_delta = num / fmaxf(2.f * q, 1.f);
        s_eps = fmaxf(mean_delta * 0.5f, 0.f);   // relu(mean_delta / K_DELTA)
    }
    __syncthreads();
    const float eps = s_eps;

    // ---- cmask: blocks 0..95 own one anchor each ----
    if (bid < NN) {
        const int ianc = bid;
        if (tid < NN) srow[tid] = g_mat[ianc * NN + tid];
        if (tid >= NN && tid < NN + 3) {
            sm[tid - NN] = g_smask[ianc * 3 + (tid - NN)];
            dm[tid - NN] = g_dmask[ianc * 3 + (tid - NN)];
        }
        __syncthreads();
        for (int p = warp; p < NN; p += 8) {
            unsigned sp = (sm[p >> 5] >> (p & 31)) & 1u;
            float matp = srow[p];
            #pragma unroll
            for (int wd = 0; wd < 3; wd++) {
                float m = srow[wd * 32 + lane] - matp;
                bool cc = sp && (((dm[wd] >> lane) & 1u) != 0u) && (m > 0.f) && (m <= eps);
                unsigned b = __ballot_sync(0xffffffffu, cc);
                if (lane == 0) g_cmask[(ianc * NN + p) * 4 + wd] = b;
            }
        }
    }
}

// ---------------------------------------------------------------------------
// writer: the proven 49us full-slab shape (R5 kC). One block per (i,j);
// stage the 96x3 AND-ed words (zeroed for k<=j) in smem; 256 threads emit
// 9 coalesced float4 each via streaming stores. Zeros fall out of the
// bit-expansion automatically -> branch-free uniform stream.
// ---------------------------------------------------------------------------
__global__ __launch_bounds__(256) void writer(float4* __restrict__ out) {
    __shared__ unsigned sw[NN * 3];
    const int r2 = blockIdx.x;           // i*96 + j
    const int j  = r2 % NN;
    const int ibase = r2 - j;            // i*96
    const int tid = threadIdx.x;

    for (int t = tid; t < NN * 3; t += 256) {
        int k  = t / 3;
        int wd = t - k * 3;
        unsigned v = 0u;
        if (k > j)
            v = g_cmask[(r2 << 2) + wd] & g_cmask[((ibase + k) << 2) + wd];
        sw[t] = v;                       // layout sw[k*3 + wd]
    }
    __syncthreads();

    float4* o = out + (size_t)r2 * 2304; // 96*96/4 float4 per (i,j)
    const unsigned ONEF = 0x3f800000u;
    #pragma unroll
    for (int p = 0; p < 9; p++) {
        int pos = p * 256 + tid;         // 0..2303
        int k   = pos / 24;              // 24 float4 per n-row
        int n4  = pos - k * 24;
        unsigned w = sw[k * 3 + (n4 >> 3)];
        unsigned b = w >> ((n4 & 7) * 4);
        float4 v;
        v.x = __uint_as_float(ONEF & (0u - (b & 1u)));
        v.y = __uint_as_float(ONEF & (0u - ((b >> 1) & 1u)));
        v.z = __uint_as_float(ONEF & (0u - ((b >> 2) & 1u)));
        v.w = __uint_as_float(ONEF & (0u - ((b >> 3) & 1u)));
        __stcs(&o[pos], v);              // streaming store: evict-first
    }
}

// ---------------------------------------------------------------------------
extern "C" void kernel_launch(void* const* d_in, const int* in_sizes, int n_in,
                              void* d_out, int out_size) {
    const float* logits = (const float*)d_in[0];   // [96,64]
    const float* labels = (const float*)d_in[1];   // [96,30]

    prep<<<PREP_BLOCKS, 256>>>(logits, labels);
    writer<<<NN * NN, 256>>>((float4*)d_out);
}

// round 13
// speedup vs baseline: 1.2475x; 1.1766x over previous
#include <cuda_runtime.h>
#include <cuda_bf16.h>
#include <stdint.h>

#define NN 96
#define DD 64
#define CC 30

// Scratch (__device__ globals; no allocation allowed)
__device__ float    g_rnum[NN], g_rq[NN];   // per-row eps partials
__device__ unsigned g_cmask[NN * NN * 4];   // 96-bit mask per (i,p), stride 4 words
__device__ unsigned g_count;                // prep barrier (monotonic; +96 per launch)

// ---------------------------------------------------------------------------
// prep: 96 blocks x 256, ONE launch, no mat round-trip through global.
// Block i owns anchor i end-to-end:
//   stage logits+labels (smem, coalesced) -> all norms + mat ROW i (smem)
//   -> row-i label masks (ballots) -> row-i eps partials (2 floats to global)
//   -> 96-block monotonic barrier -> redundant serial eps reduce (identical
//   i-ascending order in every block -> deterministic) -> cmask for anchor i.
// All reduction orders identical to the previously passing kernels.
// ---------------------------------------------------------------------------
__global__ __launch_bounds__(256) void prep(const float* __restrict__ logits,
                                            const float* __restrict__ labels) {
    __shared__ float    sx[NN * 65];     // logits, rows padded to 65
    __shared__ float    slab[NN * CC];   // labels
    __shared__ float    rn[NN];          // rsqrt norms
    __shared__ float    srow[NN];        // mat row i
    __shared__ unsigned sm[3], dm[3];    // smask/dmask row i
    __shared__ float    s_eps;

    const int tid  = threadIdx.x;
    const int ianc = blockIdx.x;         // anchor i
    const int warp = tid >> 5, lane = tid & 31;

    // ---- stage inputs (coalesced) ----
    #pragma unroll
    for (int it = 0; it < 24; it++) {                 // 6144 = 24*256
        int t = it * 256 + tid;
        sx[(t >> 6) * 65 + (t & 63)] = logits[t];
    }
    #pragma unroll
    for (int it = 0; it < 12; it++) {                 // 2880 = 96*30
        int t = it * 256 + tid;
        if (t < NN * CC) slab[t] = labels[t];
    }
    __syncthreads();

    // ---- all norms (d-ascending, same order as before) ----
    if (tid < NN) {
        float s = 0.f;
        #pragma unroll
        for (int d = 0; d < DD; d++) { float v = sx[tid * 65 + d]; s += v * v; }
        rn[tid] = rsqrtf(s);
    }
    // ---- row-i label masks (warp 1; same cc-ascending dot order) ----
    if (warp == 1) {
        #pragma unroll
        for (int wd = 0; wd < 3; wd++) {
            int j = wd * 32 + lane;
            float acc = 0.f;
            #pragma unroll
            for (int cc = 0; cc < CC; cc++) acc += slab[ianc * CC + cc] * slab[j * CC + cc];
            bool same_raw = acc > 0.f;
            unsigned sb = __ballot_sync(0xffffffffu, same_raw && (j != ianc));
            unsigned db = __ballot_sync(0xffffffffu, !same_raw);
            if (lane == 0) { sm[wd] = sb; dm[wd] = db; }
        }
    }
    __syncthreads();

    // ---- mat row i (d-ascending dot, same order/formula as before) ----
    if (tid < NN) {
        float acc = 0.f;
        #pragma unroll
        for (int d = 0; d < DD; d++) acc += sx[ianc * 65 + d] * sx[tid * 65 + d];
        srow[tid] = -acc * rn[ianc] * rn[tid];
    }
    __syncthreads();

    // ---- row-i eps partials (warp 0; identical lane/word/shuffle pattern) ----
    if (warp == 0) {
        float S = 0.f, ds = 0.f, ms = 0.f, md = 0.f;
        #pragma unroll
        for (int jj = 0; jj < 3; jj++) {
            float mv = srow[jj * 32 + lane];
            if ((sm[jj] >> lane) & 1u) { S += 1.f; ms += mv; }
            if ((dm[jj] >> lane) & 1u) { ds += 1.f; md += mv; }
        }
        #pragma unroll
        for (int o = 16; o; o >>= 1) {
            S  += __shfl_xor_sync(0xffffffffu, S,  o);
            ds += __shfl_xor_sync(0xffffffffu, ds, o);
            ms += __shfl_xor_sync(0xffffffffu, ms, o);
            md += __shfl_xor_sync(0xffffffffu, md, o);
        }
        if (lane == 0) {
            g_rnum[ianc] = (S - 1.f) * (S * md - ms * ds);
            g_rq[ianc]   = 0.5f * S * (S - 1.f) * ds;
        }
    }

    // ---- barrier among the 96 blocks (co-resident: one wave) ----
    __threadfence();                                  // publish partials
    __syncthreads();
    if (tid == 0) {
        unsigned prev   = atomicAdd(&g_count, 1u);
        unsigned target = (prev / (unsigned)NN + 1u) * (unsigned)NN;
        while (*(volatile unsigned*)&g_count < target) { }
        __threadfence();                              // acquire
    }
    __syncthreads();

    // ---- eps: redundant serial reduce, identical order in every block ----
    if (tid == 0) {
        float num = 0.f, q = 0.f;
        for (int i = 0; i < NN; i++) { num += g_rnum[i]; q += g_rq[i]; }
        float mean_delta = num / fmaxf(2.f * q, 1.f);
        s_eps = fmaxf(mean_delta * 0.5f, 0.f);   // relu(mean_delta / K_DELTA)
    }
    __syncthreads();
    const float eps = s_eps;

    // ---- cmask for anchor i (8 warps, same ballot math as before) ----
    for (int p = warp; p < NN; p += 8) {
        unsigned sp = (sm[p >> 5] >> (p & 31)) & 1u;
        float matp = srow[p];
        #pragma unroll
        for (int wd = 0; wd < 3; wd++) {
            float m = srow[wd * 32 + lane] - matp;
            bool cc = sp && (((dm[wd] >> lane) & 1u) != 0u) && (m > 0.f) && (m <= eps);
            unsigned b = __ballot_sync(0xffffffffu, cc);
            if (lane == 0) g_cmask[(ianc * NN + p) * 4 + wd] = b;
        }
    }
}

// ---------------------------------------------------------------------------
// writer: the proven 48us full-slab shape. One block per (i,j); stage the
// 96x3 AND-ed words (zeroed for k<=j) in smem; 256 threads emit 9 coalesced
// float4 each via streaming stores.
// ---------------------------------------------------------------------------
__global__ __launch_bounds__(256) void writer(float4* __restrict__ out) {
    __shared__ unsigned sw[NN * 3];
    const int r2 = blockIdx.x;           // i*96 + j
    const int j  = r2 % NN;
    const int ibase = r2 - j;            // i*96
    const int tid = threadIdx.x;

    for (int t = tid; t < NN * 3; t += 256) {
        int k  = t / 3;
        int wd = t - k * 3;
        unsigned v = 0u;
        if (k > j)
            v = g_cmask[(r2 << 2) + wd] & g_cmask[((ibase + k) << 2) + wd];
        sw[t] = v;                       // layout sw[k*3 + wd]
    }
    __syncthreads();

    float4* o = out + (size_t)r2 * 2304; // 96*96/4 float4 per (i,j)
    const unsigned ONEF = 0x3f800000u;
    #pragma unroll
    for (int p = 0; p < 9; p++) {
        int pos = p * 256 + tid;         // 0..2303
        int k   = pos / 24;              // 24 float4 per n-row
        int n4  = pos - k * 24;
        unsigned w = sw[k * 3 + (n4 >> 3)];
        unsigned b = w >> ((n4 & 7) * 4);
        float4 v;
        v.x = __uint_as_float(ONEF & (0u - (b & 1u)));
        v.y = __uint_as_float(ONEF & (0u - ((b >> 1) & 1u)));
        v.z = __uint_as_float(ONEF & (0u - ((b >> 2) & 1u)));
        v.w = __uint_as_float(ONEF & (0u - ((b >> 3) & 1u)));
        __stcs(&o[pos], v);              // streaming store: evict-first
    }
}

// ---------------------------------------------------------------------------
extern "C" void kernel_launch(void* const* d_in, const int* in_sizes, int n_in,
                              void* d_out, int out_size) {
    const float* logits = (const float*)d_in[0];   // [96,64]
    const float* labels = (const float*)d_in[1];   // [96,30]

    prep<<<NN, 256>>>(logits, labels);
    writer<<<NN * NN, 256>>>((float4*)d_out);
}

// round 14
// speedup vs baseline: 1.2552x; 1.0061x over previous
#include <cuda_runtime.h>
#include <cuda_bf16.h>
#include <stdint.h>

#define NN 96
#define DD 64
#define CC 30

// Scratch (__device__ globals; no allocation allowed)
__device__ float    g_mat[NN * NN];         // mat rows (written by prepA)
__device__ unsigned g_smask[NN * 3];
__device__ unsigned g_dmask[NN * 3];
__device__ float    g_rnum[NN], g_rq[NN];   // per-row eps partials
__device__ unsigned g_cmask[NN * NN * 4];   // 96-bit mask per (i,p), stride 4 words

// ---------------------------------------------------------------------------
// prepA: 96 blocks x 256. Block i owns anchor i. No barrier, no spin —
// the kernel boundary IS the grid barrier (measured ~free).
//   stage logits+labels (smem) -> all norms -> mat ROW i -> row-i label
//   masks (ballots) -> row-i eps partials. Persist srow/masks/partials.
// All reduction orders identical to the R13-passing kernel.
// ---------------------------------------------------------------------------
__global__ __launch_bounds__(256) void prepA(const float* __restrict__ logits,
                                             const float* __restrict__ labels) {
    __shared__ float    sx[NN * 65];     // logits, rows padded to 65
    __shared__ float    slab[NN * CC];   // labels
    __shared__ float    rn[NN];          // rsqrt norms
    __shared__ float    srow[NN];        // mat row i
    __shared__ unsigned sm[3], dm[3];    // smask/dmask row i

    const int tid  = threadIdx.x;
    const int ianc = blockIdx.x;         // anchor i
    const int warp = tid >> 5, lane = tid & 31;

    // ---- stage inputs (coalesced) ----
    #pragma unroll
    for (int it = 0; it < 24; it++) {                 // 6144 = 24*256
        int t = it * 256 + tid;
        sx[(t >> 6) * 65 + (t & 63)] = logits[t];
    }
    #pragma unroll
    for (int it = 0; it < 12; it++) {                 // 2880 = 96*30
        int t = it * 256 + tid;
        if (t < NN * CC) slab[t] = labels[t];
    }
    __syncthreads();

    // ---- all norms (d-ascending, same order as before) ----
    if (tid < NN) {
        float s = 0.f;
        #pragma unroll
        for (int d = 0; d < DD; d++) { float v = sx[tid * 65 + d]; s += v * v; }
        rn[tid] = rsqrtf(s);
    }
    // ---- row-i label masks (warp 1; same cc-ascending dot order) ----
    if (warp == 1) {
        #pragma unroll
        for (int wd = 0; wd < 3; wd++) {
            int j = wd * 32 + lane;
            float acc = 0.f;
            #pragma unroll
            for (int cc = 0; cc < CC; cc++) acc += slab[ianc * CC + cc] * slab[j * CC + cc];
            bool same_raw = acc > 0.f;
            unsigned sb = __ballot_sync(0xffffffffu, same_raw && (j != ianc));
            unsigned db = __ballot_sync(0xffffffffu, !same_raw);
            if (lane == 0) {
                sm[wd] = sb;  dm[wd] = db;
                g_smask[ianc * 3 + wd] = sb;
                g_dmask[ianc * 3 + wd] = db;
            }
        }
    }
    __syncthreads();

    // ---- mat row i (d-ascending dot, same order/formula as before) ----
    if (tid < NN) {
        float acc = 0.f;
        #pragma unroll
        for (int d = 0; d < DD; d++) acc += sx[ianc * 65 + d] * sx[tid * 65 + d];
        float v = -acc * rn[ianc] * rn[tid];
        srow[tid] = v;
        g_mat[ianc * NN + tid] = v;                  // persist for prepB
    }
    __syncthreads();

    // ---- row-i eps partials (warp 0; identical lane/word/shuffle pattern) ----
    if (warp == 0) {
        float S = 0.f, ds = 0.f, ms = 0.f, md = 0.f;
        #pragma unroll
        for (int jj = 0; jj < 3; jj++) {
            float mv = srow[jj * 32 + lane];
            if ((sm[jj] >> lane) & 1u) { S += 1.f; ms += mv; }
            if ((dm[jj] >> lane) & 1u) { ds += 1.f; md += mv; }
        }
        #pragma unroll
        for (int o = 16; o; o >>= 1) {
            S  += __shfl_xor_sync(0xffffffffu, S,  o);
            ds += __shfl_xor_sync(0xffffffffu, ds, o);
            ms += __shfl_xor_sync(0xffffffffu, ms, o);
            md += __shfl_xor_sync(0xffffffffu, md, o);
        }
        if (lane == 0) {
            g_rnum[ianc] = (S - 1.f) * (S * md - ms * ds);
            g_rq[ianc]   = 0.5f * S * (S - 1.f) * ds;
        }
    }
}

// ---------------------------------------------------------------------------
// prepB: 96 blocks x 256. Block i: redundant serial eps reduce (identical
// i-ascending order in every block -> deterministic, same value), then the
// identical cmask ballots for anchor i.
// ---------------------------------------------------------------------------
__global__ __launch_bounds__(256) void prepB() {
    __shared__ float    srow[NN];
    __shared__ unsigned sm[3], dm[3];
    __shared__ float    s_eps;

    const int tid  = threadIdx.x;
    const int ianc = blockIdx.x;
    const int warp = tid >> 5, lane = tid & 31;

    if (tid < NN) srow[tid] = g_mat[ianc * NN + tid];
    if (tid >= NN && tid < NN + 3) {
        sm[tid - NN] = g_smask[ianc * 3 + (tid - NN)];
        dm[tid - NN] = g_dmask[ianc * 3 + (tid - NN)];
    }
    if (tid == 128) {   // serial reduce: identical order in every block
        float num = 0.f, q = 0.f;
        for (int i = 0; i < NN; i++) { num += g_rnum[i]; q += g_rq[i]; }
        float mean_delta = num / fmaxf(2.f * q, 1.f);
        s_eps = fmaxf(mean_delta * 0.5f, 0.f);   // relu(mean_delta / K_DELTA)
    }
    __syncthreads();
    const float eps = s_eps;

    // ---- cmask for anchor i (8 warps, same ballot math as before) ----
    for (int p = warp; p < NN; p += 8) {
        unsigned sp = (sm[p >> 5] >> (p & 31)) & 1u;
        float matp = srow[p];
        #pragma unroll
        for (int wd = 0; wd < 3; wd++) {
            float m = srow[wd * 32 + lane] - matp;
            bool cc = sp && (((dm[wd] >> lane) & 1u) != 0u) && (m > 0.f) && (m <= eps);
            unsigned b = __ballot_sync(0xffffffffu, cc);
            if (lane == 0) g_cmask[(ianc * NN + p) * 4 + wd] = b;
        }
    }
}

// ---------------------------------------------------------------------------
// writer: the proven 48us full-slab shape. One block per (i,j); stage the
// 96x3 AND-ed words (zeroed for k<=j) in smem; 256 threads emit 9 coalesced
// float4 each via streaming stores.
// ---------------------------------------------------------------------------
__global__ __launch_bounds__(256) void writer(float4* __restrict__ out) {
    __shared__ unsigned sw[NN * 3];
    const int r2 = blockIdx.x;           // i*96 + j
    const int j  = r2 % NN;
    const int ibase = r2 - j;            // i*96
    const int tid = threadIdx.x;

    for (int t = tid; t < NN * 3; t += 256) {
        int k  = t / 3;
        int wd = t - k * 3;
        unsigned v = 0u;
        if (k > j)
            v = g_cmask[(r2 << 2) + wd] & g_cmask[((ibase + k) << 2) + wd];
        sw[t] = v;                       // layout sw[k*3 + wd]
    }
    __syncthreads();

    float4* o = out + (size_t)r2 * 2304; // 96*96/4 float4 per (i,j)
    const unsigned ONEF = 0x3f800000u;
    #pragma unroll
    for (int p = 0; p < 9; p++) {
        int pos = p * 256 + tid;         // 0..2303
        int k   = pos / 24;              // 24 float4 per n-row
        int n4  = pos - k * 24;
        unsigned w = sw[k * 3 + (n4 >> 3)];
        unsigned b = w >> ((n4 & 7) * 4);
        float4 v;
        v.x = __uint_as_float(ONEF & (0u - (b & 1u)));
        v.y = __uint_as_float(ONEF & (0u - ((b >> 1) & 1u)));
        v.z = __uint_as_float(ONEF & (0u - ((b >> 2) & 1u)));
        v.w = __uint_as_float(ONEF & (0u - ((b >> 3) & 1u)));
        __stcs(&o[pos], v);              // streaming store: evict-first
    }
}

// ---------------------------------------------------------------------------
extern "C" void kernel_launch(void* const* d_in, const int* in_sizes, int n_in,
                              void* d_out, int out_size) {
    const float* logits = (const float*)d_in[0];   // [96,64]
    const float* labels = (const float*)d_in[1];   // [96,30]

    prepA<<<NN, 256>>>(logits, labels);
    prepB<<<NN, 256>>>();
    writer<<<NN * NN, 256>>>((float4*)d_out);
}